// round 15
// baseline (speedup 1.0000x reference)
#include <cuda_runtime.h>
#include <cuda_fp16.h>
#include <cstdint>

// ===========================================================================
// BrickVectorEdgeModel — single-term fp16 mma.sync, M=128 tiles, cp.async s1
//   stage1 (SIMT fp32, cp.async W ping-pong): u, v
//   prep:   Wcb/Wcc -> fp16, permuted 16KB piece blobs (128 rows x 64 k)
//   layer1: e0 = relu(v_i + u_j + b_ca) fp16 in smem (128 rows);
//           e1 = relu(e0@Wcb^T + b_cb) -> global fp16 blob (coalesced)
//   layer2: e2 = relu(e1@Wcc^T + b_cc); fused @W_out + b_out
// ===========================================================================

#define HD 512
#define TILE_M 128
#define N_TILES 1152           // 147456 / 128

__device__ float g_u[768 * HD];
__device__ float g_v[768 * HD];
__device__ float g_f1[768 * HD];
__device__ float g_f2[768 * HD];
__device__ char  g_wcb_h[524288];      // 512x512 fp16, 16KB-piece blob layout
__device__ char  g_wcc_h[524288];
__device__ char  g_e1_h[150994944];    // 1152 tiles * 128 rows * 1024B

extern __shared__ char s_raw[];

// ---------------- PTX helpers ----------------------------------------------
__device__ __forceinline__ uint32_t smem_u32(const void* p) {
    uint32_t a;
    asm("{ .reg .u64 t; cvta.to.shared.u64 t, %1; cvt.u32.u64 %0, t; }"
        : "=r"(a) : "l"(p));
    return a;
}
__device__ __forceinline__ void cp16(uint32_t d, const void* s) {
    asm volatile("cp.async.cg.shared.global [%0], [%1], 16;" :: "r"(d), "l"(s));
}
__device__ __forceinline__ void cp_commit() { asm volatile("cp.async.commit_group;"); }
__device__ __forceinline__ void cp_wait1()  { asm volatile("cp.async.wait_group 1;"); }
__device__ __forceinline__ void cp_wait0()  { asm volatile("cp.async.wait_group 0;"); }

__device__ __forceinline__ void ldsm_x4(uint32_t* r, uint32_t a) {
    asm volatile("ldmatrix.sync.aligned.m8n8.x4.shared.b16 {%0,%1,%2,%3}, [%4];"
                 : "=r"(r[0]), "=r"(r[1]), "=r"(r[2]), "=r"(r[3]) : "r"(a));
}
__device__ __forceinline__ void mma16816(float* d, const uint32_t* a,
                                         const uint32_t* b) {
    asm volatile("mma.sync.aligned.m16n8k16.row.col.f32.f16.f16.f32 "
                 "{%0,%1,%2,%3}, {%4,%5,%6,%7}, {%8,%9}, {%0,%1,%2,%3};"
                 : "+f"(d[0]), "+f"(d[1]), "+f"(d[2]), "+f"(d[3])
                 : "r"(a[0]), "r"(a[1]), "r"(a[2]), "r"(a[3]),
                   "r"(b[0]), "r"(b[1]));
}
__device__ __forceinline__ uint32_t pkh(__half a, __half b) {
    return (uint32_t)__half_as_ushort(a) |
           ((uint32_t)__half_as_ushort(b) << 16);
}

// A-tile permuted row layout: 1024B rows, 16B chunks, chunk ^= (row & 7)
__device__ __forceinline__ uint32_t prow(int row, int chunk) {
    return (uint32_t)(row * 1024 + ((chunk ^ (row & 7)) << 4));
}
// 256B-row permuted layout (e1 staging)
__device__ __forceinline__ uint32_t prow256(int row, int chunk) {
    return (uint32_t)(row * 256 + ((chunk ^ (row & 7)) << 4));
}
// 128B-row permuted layout (W pieces: 128 rows x 64 k)
__device__ __forceinline__ uint32_t prow128(int row, int chunk) {
    return (uint32_t)(row * 128 + ((chunk ^ (row & 7)) << 4));
}

// ---------------- fp32x2 helpers (stage1) ----------------------------------
__device__ __forceinline__ unsigned long long pack2(float x, float y) {
    unsigned long long r;
    asm("mov.b64 %0, {%1, %2};" : "=l"(r) : "f"(x), "f"(y));
    return r;
}
__device__ __forceinline__ void ffma2(unsigned long long& d,
                                      unsigned long long a, unsigned long long b) {
    asm("fma.rn.f32x2 %0, %1, %2, %0;" : "+l"(d) : "l"(a), "l"(b));
}
__device__ __forceinline__ float2 unpack2(unsigned long long v) {
    float2 f;
    asm("mov.b64 {%0, %1}, %2;" : "=f"(f.x), "=f"(f.y) : "l"(v));
    return f;
}

// ---------------- stage1: one 128-col tile, cp.async W ping-pong -----------
// smem floats: A[4096] | wt0[4608] | wt1[4608] | sout[1024]  -> 57344 B
template <bool BIAS>
__device__ __forceinline__ void layer_tile8(const float* __restrict__ in,
                                            const float* __restrict__ Wg,
                                            int wstride, int nt,
                                            const float* __restrict__ bias,
                                            float* __restrict__ sout,
                                            float* __restrict__ wt,
                                            uint32_t wt_addr) {
    const int tid = threadIdx.x, lane = tid & 31, warp = tid >> 5;
    const int ch = warp & 1, rg = warp >> 1;
    const int rbase = rg * 2;
    unsigned long long acc[2][2];
#pragma unroll
    for (int rr = 0; rr < 2; ++rr) { acc[rr][0] = 0ull; acc[rr][1] = 0ull; }

    // prologue: issue kt=0 into wt buffer 0
#pragma unroll
    for (int s = 0; s < 4; ++s) {
        int idx = tid + s * 256;          // 1024 granules
        int c = idx >> 3, k4 = idx & 7;
        cp16(wt_addr + c * 144 + k4 * 16,
             &Wg[(nt * 128 + c) * wstride + k4 * 4]);
    }
    cp_commit();

    for (int kt = 0; kt < 16; ++kt) {
        const int buf = kt & 1;
        if (kt + 1 < 16) {
            uint32_t db = wt_addr + (buf ^ 1) * 18432;
#pragma unroll
            for (int s = 0; s < 4; ++s) {
                int idx = tid + s * 256;
                int c = idx >> 3, k4 = idx & 7;
                cp16(db + c * 144 + k4 * 16,
                     &Wg[(nt * 128 + c) * wstride + (kt + 1) * 32 + k4 * 4]);
            }
            cp_commit();
            cp_wait1();
        } else {
            cp_wait0();
        }
        __syncthreads();

        const float* wb = wt + buf * 4608;
        const float* inb = in + kt * 32;
#pragma unroll
        for (int kk = 0; kk < 32; kk += 4) {
            unsigned long long w01[2], w23[2];
#pragma unroll
            for (int cc = 0; cc < 2; ++cc) {
                int cl = ch * 64 + cc * 32 + lane;
                float4 w = *(const float4*)&wb[cl * 36 + kk];
                w01[cc] = pack2(w.x, w.y);
                w23[cc] = pack2(w.z, w.w);
            }
#pragma unroll
            for (int rr = 0; rr < 2; ++rr) {
                float4 a = *(const float4*)&inb[(rbase + rr) * 512 + kk];
                unsigned long long a01 = pack2(a.x, a.y);
                unsigned long long a23 = pack2(a.z, a.w);
#pragma unroll
                for (int cc = 0; cc < 2; ++cc) {
                    ffma2(acc[rr][cc], a01, w01[cc]);
                    ffma2(acc[rr][cc], a23, w23[cc]);
                }
            }
        }
        __syncthreads();
    }
#pragma unroll
    for (int cc = 0; cc < 2; ++cc) {
        int cl = ch * 64 + cc * 32 + lane;
        float bval = BIAS ? bias[nt * 128 + cl] : 0.0f;
#pragma unroll
        for (int rr = 0; rr < 2; ++rr) {
            float2 s = unpack2(acc[rr][cc]);
            sout[(rbase + rr) * 128 + cl] = s.x + s.y + bval;
        }
    }
}

#define S1_SMEM 57344

__global__ void __launch_bounds__(256, 1)
s1_f1_kernel(const float* __restrict__ brick, const float* __restrict__ xy,
             const float* __restrict__ Wxy, const float* __restrict__ bxy,
             const float* __restrict__ Wa, const float* __restrict__ ba) {
    float* sm = (float*)s_raw;
    float* A = sm;
    float* wt = sm + 4096;
    float* sout = sm + 13312;
    uint32_t wt_addr = smem_u32(wt);
    const int r0 = blockIdx.x * 8, nt = blockIdx.y;
    for (int idx = threadIdx.x; idx < 8 * 128; idx += 256) {
        int m = idx >> 7, q = idx & 127;
        *(float4*)&A[m * 512 + q * 4] =
            *(const float4*)&brick[(size_t)(r0 + m) * 512 + q * 4];
    }
    layer_tile8<true>(A, Wa, 512, nt, ba, sout, wt, wt_addr);
    __syncthreads();
    for (int idx = threadIdx.x; idx < 8 * 128; idx += 256) {
        int m = idx >> 7, c = idx & 127, h = nt * 128 + c;
        float x0 = xy[(r0 + m) * 2 + 0];
        float x1 = xy[(r0 + m) * 2 + 1];
        float val = sout[m * 128 + c] + x0 * Wxy[h * 2] + x1 * Wxy[h * 2 + 1] + bxy[h];
        g_f1[(size_t)(r0 + m) * 512 + h] = fmaxf(val, 0.0f);
    }
}

__global__ void __launch_bounds__(256, 1)
s1_f2_kernel(const float* __restrict__ Wb, const float* __restrict__ bb) {
    float* sm = (float*)s_raw;
    float* A = sm;
    float* wt = sm + 4096;
    float* sout = sm + 13312;
    uint32_t wt_addr = smem_u32(wt);
    const int r0 = blockIdx.x * 8, nt = blockIdx.y;
    for (int idx = threadIdx.x; idx < 8 * 128; idx += 256) {
        int m = idx >> 7, q = idx & 127;
        *(float4*)&A[m * 512 + q * 4] =
            *(const float4*)&g_f1[(size_t)(r0 + m) * 512 + q * 4];
    }
    layer_tile8<true>(A, Wb, 512, nt, bb, sout, wt, wt_addr);
    __syncthreads();
    for (int idx = threadIdx.x; idx < 8 * 128; idx += 256) {
        int m = idx >> 7, c = idx & 127;
        g_f2[(size_t)(r0 + m) * 512 + nt * 128 + c] =
            fmaxf(sout[m * 128 + c], 0.0f);
    }
}

__global__ void __launch_bounds__(256, 1)
s1_uv_kernel(const float* __restrict__ Wca) {
    float* sm = (float*)s_raw;
    float* A = sm;
    float* wt = sm + 4096;
    float* sout = sm + 13312;
    uint32_t wt_addr = smem_u32(wt);
    const int r0 = blockIdx.x * 8;
    const int half = blockIdx.y >> 2, nt = blockIdx.y & 3;
    for (int idx = threadIdx.x; idx < 8 * 128; idx += 256) {
        int m = idx >> 7, q = idx & 127;
        *(float4*)&A[m * 512 + q * 4] =
            *(const float4*)&g_f2[(size_t)(r0 + m) * 512 + q * 4];
    }
    layer_tile8<false>(A, Wca + half * 512, 1024, nt, nullptr, sout, wt, wt_addr);
    __syncthreads();
    float* dst = half ? g_v : g_u;
    for (int idx = threadIdx.x; idx < 8 * 128; idx += 256) {
        int m = idx >> 7, c = idx & 127;
        dst[(size_t)(r0 + m) * 512 + nt * 128 + c] = sout[m * 128 + c];
    }
}

// ---------------- prep: fp16-convert + permute weights ---------------------
// piece p = nc*8 + kq (16KB): rows r=0..127 (n = nc*128+r), k = kq*64..+64.
__global__ void prep_kernel(const float* __restrict__ Wcb,
                            const float* __restrict__ Wcc) {
    int gid = blockIdx.x * 256 + threadIdx.x;   // 65536 threads
    for (int e = gid; e < 262144; e += 65536) {
        int n = e >> 9, k = e & 511;
        int nc = n >> 7, r = n & 127, kq = k >> 6, kk = k & 63;
        int c = kk >> 3, w = kk & 7;
        uint32_t dst = (uint32_t)((nc * 8 + kq) * 16384 + r * 128 +
                                  ((c ^ (r & 7)) << 4) + w * 2);
        *(__half*)(g_wcb_h + dst) = __float2half_rn(Wcb[e]);
        *(__half*)(g_wcc_h + dst) = __float2half_rn(Wcc[e]);
    }
}

// ---------------- layer kernels (M=128, 512 threads) -----------------------
// layer1 smem: A 0..128K, Wbuf[2] 128..160K, stage 160..192K (196608 B)
// layer2 smem: A 0..128K, Wbuf[2] 128..160K, Wout, red       (172032 B)
#define SM_A     0
#define SM_WB(b) (131072 + (b) * 16384)
#define SM_STG   163840
#define SM_WOUT  163840
#define SM_RED   167936
#define SMEM1_BYTES 196608
#define SMEM2_BYTES 172032

template <int LAYER>
__global__ void __launch_bounds__(512, 1)
layer_kernel(const float* __restrict__ bca, const float* __restrict__ bias,
             const float* __restrict__ Wout, const float* __restrict__ bout,
             float* __restrict__ out) {
    char* sm = s_raw;
    const uint32_t smem = smem_u32(sm);
    const int tid = threadIdx.x, wid = tid >> 5, lane = tid & 31;
    const int tile = blockIdx.x;
    const int wm = wid & 3;          // M quarter (32 rows)
    const int wn = wid >> 2;         // N quarter (32 cols of 128-chunk)

    const char* wsrc = (LAYER == 1) ? g_wcb_h : g_wcc_h;

    // -- prologue: W piece 0 (16KB) async; layer2 also A tile (128KB) --
    {
#pragma unroll
        for (int s = 0; s < 2; ++s) {
            int g2 = tid + s * 512;          // 1024 granules
            cp16(smem + SM_WB(0) + g2 * 16, wsrc + g2 * 16);
        }
        if (LAYER == 2) {
            const char* srch = g_e1_h + (size_t)tile * 131072;
#pragma unroll
            for (int s = 0; s < 16; ++s) {
                int o = (tid + s * 512) * 16;   // 8192 granules
                cp16(smem + SM_A + o, srch + o);
            }
            if (tid < 256)
                *(float4*)(sm + SM_WOUT + tid * 16) = *(const float4*)&Wout[tid * 4];
        }
        cp_commit();
    }
    if (LAYER == 1) {
        // build e0 tile (fp16): row r = tid>>2, chunks (tid&3)*16 + s
        const int r = tid >> 2;
        const int p = tile * TILE_M + r;
        const int b = p / 36864;
        const int rem = p - b * 36864;
        const int i = rem / 192, j = rem - i * 192;
        const float* up = g_u + (size_t)(b * 192 + j) * HD;
        const float* vp = g_v + (size_t)(b * 192 + i) * HD;
        const int cb = (tid & 3) * 16;
#pragma unroll
        for (int s = 0; s < 16; ++s) {
            int chunk = cb + s, k0 = chunk * 8;
            float4 u0 = *(const float4*)(up + k0);
            float4 u1 = *(const float4*)(up + k0 + 4);
            float4 v0 = *(const float4*)(vp + k0);
            float4 v1 = *(const float4*)(vp + k0 + 4);
            float4 c0 = *(const float4*)(bca + k0);
            float4 c1 = *(const float4*)(bca + k0 + 4);
            float x[8] = {u0.x + v0.x + c0.x, u0.y + v0.y + c0.y,
                          u0.z + v0.z + c0.z, u0.w + v0.w + c0.w,
                          u1.x + v1.x + c1.x, u1.y + v1.y + c1.y,
                          u1.z + v1.z + c1.z, u1.w + v1.w + c1.w};
            uint32_t hi4[4];
#pragma unroll
            for (int t = 0; t < 4; ++t) {
                float a0 = fmaxf(x[2 * t], 0.0f);
                float a1 = fmaxf(x[2 * t + 1], 0.0f);
                hi4[t] = pkh(__float2half_rn(a0), __float2half_rn(a1));
            }
            uint32_t off = prow(r, chunk);
            *(uint4*)(sm + SM_A + off) = make_uint4(hi4[0], hi4[1], hi4[2], hi4[3]);
        }
    }

    // lane constants for ldmatrix addressing
    const int a_row = wm * 32 + (lane & 15);
    const int a_half = lane >> 4;
    const int w_rl = (lane & 7) + ((lane >> 4) << 3);
    const int w_half = (lane >> 3) & 1;

    float head[2][2][2];
#pragma unroll
    for (int a2 = 0; a2 < 2; ++a2)
#pragma unroll
        for (int b2 = 0; b2 < 2; ++b2) { head[a2][b2][0] = 0.f; head[a2][b2][1] = 0.f; }

    float acc[2][4][4];

    for (int q = 0; q < 32; ++q) {          // nc = q>>3, kq = q&7 (64 k each)
        const int nc = q >> 3, kq = q & 7, buf = q & 1;
        if (q + 1 < 32) {
            const char* src = wsrc + (size_t)(q + 1) * 16384;
            uint32_t db = smem + SM_WB(buf ^ 1);
#pragma unroll
            for (int s = 0; s < 2; ++s) {
                int g2 = tid + s * 512;
                cp16(db + g2 * 16, src + g2 * 16);
            }
            cp_commit();
            cp_wait1();
        } else {
            cp_wait0();
        }
        __syncthreads();

        if (kq == 0) {
#pragma unroll
            for (int mt = 0; mt < 2; ++mt)
#pragma unroll
                for (int nt = 0; nt < 4; ++nt)
#pragma unroll
                    for (int e = 0; e < 4; ++e) acc[mt][nt][e] = 0.f;
        }

        const uint32_t wb = smem + SM_WB(buf);
#pragma unroll
        for (int k16 = 0; k16 < 4; ++k16) {
            uint32_t ah[2][4], wh[2][4];
            const int achunk = kq * 8 + k16 * 2 + a_half;
#pragma unroll
            for (int mt = 0; mt < 2; ++mt) {
                int row = a_row + mt * 16;
                ldsm_x4(ah[mt], smem + SM_A + prow(row, achunk));
            }
#pragma unroll
            for (int nt = 0; nt < 2; ++nt) {
                int rl = wn * 32 + nt * 16 + w_rl;
                int cc = k16 * 2 + w_half;
                ldsm_x4(wh[nt], wb + prow128(rl, cc));
            }
#pragma unroll
            for (int mt = 0; mt < 2; ++mt)
#pragma unroll
                for (int n8 = 0; n8 < 4; ++n8) {
                    const uint32_t* b2 = &wh[n8 >> 1][(n8 & 1) * 2];
                    mma16816(acc[mt][n8], ah[mt], b2);
                }
        }

        if (kq == 7) {
            // epilogue for this nc
#pragma unroll
            for (int mt = 0; mt < 2; ++mt)
#pragma unroll
                for (int n8 = 0; n8 < 4; ++n8)
#pragma unroll
                    for (int rh = 0; rh < 2; ++rh) {
                        int row = wm * 32 + mt * 16 + (lane >> 2) + rh * 8;
                        int lcol = wn * 32 + n8 * 8 + (lane & 3) * 2;
                        int col = nc * 128 + lcol;
                        float v0 = acc[mt][n8][rh * 2 + 0] + bias[col];
                        float v1 = acc[mt][n8][rh * 2 + 1] + bias[col + 1];
                        v0 = fmaxf(v0, 0.0f);
                        v1 = fmaxf(v1, 0.0f);
                        if (LAYER == 1) {
                            uint32_t off = prow256(row, lcol >> 3) +
                                           (uint32_t)((lcol & 7) * 2);
                            *(uint32_t*)(sm + SM_STG + off) =
                                pkh(__float2half_rn(v0), __float2half_rn(v1));
                        } else {
                            const float* wo = (const float*)(sm + SM_WOUT);
                            head[mt][rh][0] = fmaf(v0, wo[col], head[mt][rh][0]);
                            head[mt][rh][0] = fmaf(v1, wo[col + 1], head[mt][rh][0]);
                            head[mt][rh][1] = fmaf(v0, wo[512 + col], head[mt][rh][1]);
                            head[mt][rh][1] = fmaf(v1, wo[512 + col + 1], head[mt][rh][1]);
                        }
                    }
            if (LAYER == 1) {
                // coalesced copy: stage (128 rows x 256B) -> global blob
                __syncthreads();
                for (int idx = tid; idx < 2048; idx += 512) {
                    int row = idx >> 4, qq = idx & 15;
                    uint4 vh = *(uint4*)(sm + SM_STG + row * 256 + qq * 16);
                    size_t dst = (size_t)tile * 131072 + (size_t)row * 1024 +
                                 (size_t)nc * 256 + qq * 16;
                    *(uint4*)(g_e1_h + dst) = vh;
                }
            }
        }
        __syncthreads();
    }

    if (LAYER == 2) {
        float* red = (float*)(sm + SM_RED);   // [wn][128][2]
#pragma unroll
        for (int mt = 0; mt < 2; ++mt)
#pragma unroll
            for (int rh = 0; rh < 2; ++rh)
#pragma unroll
                for (int o = 0; o < 2; ++o) {
                    float s = head[mt][rh][o];
                    s += __shfl_xor_sync(0xffffffffu, s, 1);
                    s += __shfl_xor_sync(0xffffffffu, s, 2);
                    if ((lane & 3) == 0) {
                        int row = wm * 32 + mt * 16 + (lane >> 2) + rh * 8;
                        red[wn * 256 + row * 2 + o] = s;
                    }
                }
        __syncthreads();
        if (tid < 256) {
            int row = tid >> 1, o = tid & 1;
            float s = red[row * 2 + o] + red[256 + row * 2 + o] +
                      red[512 + row * 2 + o] + red[768 + row * 2 + o] + bout[o];
            size_t p = (size_t)tile * TILE_M + row;
            out[p * 2 + o] = s;
        }
    }
}

// ---------------------------------------------------------------------------
extern "C" void kernel_launch(void* const* d_in, const int* in_sizes, int n_in,
                              void* d_out, int out_size) {
    const float* brick = (const float*)d_in[0];
    const float* xy    = (const float*)d_in[1];
    const float* Wxy   = (const float*)d_in[2];
    const float* bxy   = (const float*)d_in[3];
    const float* Wa    = (const float*)d_in[4];
    const float* ba    = (const float*)d_in[5];
    const float* Wb    = (const float*)d_in[6];
    const float* bb    = (const float*)d_in[7];
    const float* Wca   = (const float*)d_in[8];
    const float* bca   = (const float*)d_in[9];
    const float* Wcb   = (const float*)d_in[10];
    const float* bcb   = (const float*)d_in[11];
    const float* Wcc   = (const float*)d_in[12];
    const float* bcc   = (const float*)d_in[13];
    const float* Wout  = (const float*)d_in[14];
    const float* bout  = (const float*)d_in[15];
    float* out = (float*)d_out;

    cudaFuncSetAttribute(s1_f1_kernel,
                         cudaFuncAttributeMaxDynamicSharedMemorySize, S1_SMEM);
    cudaFuncSetAttribute(s1_f2_kernel,
                         cudaFuncAttributeMaxDynamicSharedMemorySize, S1_SMEM);
    cudaFuncSetAttribute(s1_uv_kernel,
                         cudaFuncAttributeMaxDynamicSharedMemorySize, S1_SMEM);
    cudaFuncSetAttribute(layer_kernel<1>,
                         cudaFuncAttributeMaxDynamicSharedMemorySize, SMEM1_BYTES);
    cudaFuncSetAttribute(layer_kernel<2>,
                         cudaFuncAttributeMaxDynamicSharedMemorySize, SMEM2_BYTES);

    prep_kernel<<<256, 256>>>(Wcb, Wcc);
    s1_f1_kernel<<<dim3(96, 4), 256, S1_SMEM>>>(brick, xy, Wxy, bxy, Wa, ba);
    s1_f2_kernel<<<dim3(96, 4), 256, S1_SMEM>>>(Wb, bb);
    s1_uv_kernel<<<dim3(96, 8), 256, S1_SMEM>>>(Wca);
    layer_kernel<1><<<N_TILES, 512, SMEM1_BYTES>>>(bca, bcb, nullptr, nullptr, nullptr);
    layer_kernel<2><<<N_TILES, 512, SMEM2_BYTES>>>(bca, bcc, Wout, bout, out);
}

// round 16
// speedup vs baseline: 1.0693x; 1.0693x over previous
#include <cuda_runtime.h>
#include <cuda_fp16.h>
#include <cstdint>

// ===========================================================================
// BrickVectorEdgeModel — single-term fp16 mma.sync (R13 layers, M=64, 2 CTA/SM)
//   + cp.async-pipelined stage1 (R14)
// ===========================================================================

#define HD 512
#define TILE_M 64
#define N_TILES2 2304          // 147456 / 64

__device__ float g_u[768 * HD];
__device__ float g_v[768 * HD];
__device__ float g_f1[768 * HD];
__device__ float g_f2[768 * HD];
__device__ char  g_wcb_h[524288];      // 512x512 fp16, 16KB-piece blob layout
__device__ char  g_wcc_h[524288];
__device__ char  g_e1_h[150994944];    // 2304 tiles * 64 rows * 1024B

extern __shared__ char s_raw[];

// ---------------- PTX helpers ----------------------------------------------
__device__ __forceinline__ uint32_t smem_u32(const void* p) {
    uint32_t a;
    asm("{ .reg .u64 t; cvta.to.shared.u64 t, %1; cvt.u32.u64 %0, t; }"
        : "=r"(a) : "l"(p));
    return a;
}
__device__ __forceinline__ void cp16(uint32_t d, const void* s) {
    asm volatile("cp.async.cg.shared.global [%0], [%1], 16;" :: "r"(d), "l"(s));
}
__device__ __forceinline__ void cp_commit() { asm volatile("cp.async.commit_group;"); }
__device__ __forceinline__ void cp_wait1()  { asm volatile("cp.async.wait_group 1;"); }
__device__ __forceinline__ void cp_wait0()  { asm volatile("cp.async.wait_group 0;"); }

__device__ __forceinline__ void ldsm_x4(uint32_t* r, uint32_t a) {
    asm volatile("ldmatrix.sync.aligned.m8n8.x4.shared.b16 {%0,%1,%2,%3}, [%4];"
                 : "=r"(r[0]), "=r"(r[1]), "=r"(r[2]), "=r"(r[3]) : "r"(a));
}
__device__ __forceinline__ void mma16816(float* d, const uint32_t* a,
                                         const uint32_t* b) {
    asm volatile("mma.sync.aligned.m16n8k16.row.col.f32.f16.f16.f32 "
                 "{%0,%1,%2,%3}, {%4,%5,%6,%7}, {%8,%9}, {%0,%1,%2,%3};"
                 : "+f"(d[0]), "+f"(d[1]), "+f"(d[2]), "+f"(d[3])
                 : "r"(a[0]), "r"(a[1]), "r"(a[2]), "r"(a[3]),
                   "r"(b[0]), "r"(b[1]));
}
__device__ __forceinline__ uint32_t pkh(__half a, __half b) {
    return (uint32_t)__half_as_ushort(a) |
           ((uint32_t)__half_as_ushort(b) << 16);
}

// A-tile permuted row layout: 1024B rows, 16B chunks, chunk ^= (row & 7)
__device__ __forceinline__ uint32_t prow(int row, int chunk) {
    return (uint32_t)(row * 1024 + ((chunk ^ (row & 7)) << 4));
}
// 256B-row permuted layout (e1 staging)
__device__ __forceinline__ uint32_t prow256(int row, int chunk) {
    return (uint32_t)(row * 256 + ((chunk ^ (row & 7)) << 4));
}
// 128B-row permuted layout (W pieces: 128 rows x 64 k)
__device__ __forceinline__ uint32_t prow128(int row, int chunk) {
    return (uint32_t)(row * 128 + ((chunk ^ (row & 7)) << 4));
}

// ---------------- fp32x2 helpers (stage1) ----------------------------------
__device__ __forceinline__ unsigned long long pack2(float x, float y) {
    unsigned long long r;
    asm("mov.b64 %0, {%1, %2};" : "=l"(r) : "f"(x), "f"(y));
    return r;
}
__device__ __forceinline__ void ffma2(unsigned long long& d,
                                      unsigned long long a, unsigned long long b) {
    asm("fma.rn.f32x2 %0, %1, %2, %0;" : "+l"(d) : "l"(a), "l"(b));
}
__device__ __forceinline__ float2 unpack2(unsigned long long v) {
    float2 f;
    asm("mov.b64 {%0, %1}, %2;" : "=f"(f.x), "=f"(f.y) : "l"(v));
    return f;
}

// ---------------- stage1: one 128-col tile, cp.async W ping-pong -----------
// smem floats: A[4096] | wt0[4608] | wt1[4608] | sout[1024]  -> 57344 B
template <bool BIAS>
__device__ __forceinline__ void layer_tile8(const float* __restrict__ in,
                                            const float* __restrict__ Wg,
                                            int wstride, int nt,
                                            const float* __restrict__ bias,
                                            float* __restrict__ sout,
                                            float* __restrict__ wt,
                                            uint32_t wt_addr) {
    const int tid = threadIdx.x, lane = tid & 31, warp = tid >> 5;
    const int ch = warp & 1, rg = warp >> 1;
    const int rbase = rg * 2;
    unsigned long long acc[2][2];
#pragma unroll
    for (int rr = 0; rr < 2; ++rr) { acc[rr][0] = 0ull; acc[rr][1] = 0ull; }

    // prologue: issue kt=0 into wt buffer 0
#pragma unroll
    for (int s = 0; s < 4; ++s) {
        int idx = tid + s * 256;          // 1024 granules
        int c = idx >> 3, k4 = idx & 7;
        cp16(wt_addr + c * 144 + k4 * 16,
             &Wg[(nt * 128 + c) * wstride + k4 * 4]);
    }
    cp_commit();

    for (int kt = 0; kt < 16; ++kt) {
        const int buf = kt & 1;
        if (kt + 1 < 16) {
            uint32_t db = wt_addr + (buf ^ 1) * 18432;
#pragma unroll
            for (int s = 0; s < 4; ++s) {
                int idx = tid + s * 256;
                int c = idx >> 3, k4 = idx & 7;
                cp16(db + c * 144 + k4 * 16,
                     &Wg[(nt * 128 + c) * wstride + (kt + 1) * 32 + k4 * 4]);
            }
            cp_commit();
            cp_wait1();
        } else {
            cp_wait0();
        }
        __syncthreads();

        const float* wb = wt + buf * 4608;
        const float* inb = in + kt * 32;
#pragma unroll
        for (int kk = 0; kk < 32; kk += 4) {
            unsigned long long w01[2], w23[2];
#pragma unroll
            for (int cc = 0; cc < 2; ++cc) {
                int cl = ch * 64 + cc * 32 + lane;
                float4 w = *(const float4*)&wb[cl * 36 + kk];
                w01[cc] = pack2(w.x, w.y);
                w23[cc] = pack2(w.z, w.w);
            }
#pragma unroll
            for (int rr = 0; rr < 2; ++rr) {
                float4 a = *(const float4*)&inb[(rbase + rr) * 512 + kk];
                unsigned long long a01 = pack2(a.x, a.y);
                unsigned long long a23 = pack2(a.z, a.w);
#pragma unroll
                for (int cc = 0; cc < 2; ++cc) {
                    ffma2(acc[rr][cc], a01, w01[cc]);
                    ffma2(acc[rr][cc], a23, w23[cc]);
                }
            }
        }
        __syncthreads();
    }
#pragma unroll
    for (int cc = 0; cc < 2; ++cc) {
        int cl = ch * 64 + cc * 32 + lane;
        float bval = BIAS ? bias[nt * 128 + cl] : 0.0f;
#pragma unroll
        for (int rr = 0; rr < 2; ++rr) {
            float2 s = unpack2(acc[rr][cc]);
            sout[(rbase + rr) * 128 + cl] = s.x + s.y + bval;
        }
    }
}

#define S1_SMEM 57344

__global__ void __launch_bounds__(256, 1)
s1_f1_kernel(const float* __restrict__ brick, const float* __restrict__ xy,
             const float* __restrict__ Wxy, const float* __restrict__ bxy,
             const float* __restrict__ Wa, const float* __restrict__ ba) {
    float* sm = (float*)s_raw;
    float* A = sm;
    float* wt = sm + 4096;
    float* sout = sm + 13312;
    uint32_t wt_addr = smem_u32(wt);
    const int r0 = blockIdx.x * 8, nt = blockIdx.y;
    for (int idx = threadIdx.x; idx < 8 * 128; idx += 256) {
        int m = idx >> 7, q = idx & 127;
        *(float4*)&A[m * 512 + q * 4] =
            *(const float4*)&brick[(size_t)(r0 + m) * 512 + q * 4];
    }
    layer_tile8<true>(A, Wa, 512, nt, ba, sout, wt, wt_addr);
    __syncthreads();
    for (int idx = threadIdx.x; idx < 8 * 128; idx += 256) {
        int m = idx >> 7, c = idx & 127, h = nt * 128 + c;
        float x0 = xy[(r0 + m) * 2 + 0];
        float x1 = xy[(r0 + m) * 2 + 1];
        float val = sout[m * 128 + c] + x0 * Wxy[h * 2] + x1 * Wxy[h * 2 + 1] + bxy[h];
        g_f1[(size_t)(r0 + m) * 512 + h] = fmaxf(val, 0.0f);
    }
}

__global__ void __launch_bounds__(256, 1)
s1_f2_kernel(const float* __restrict__ Wb, const float* __restrict__ bb) {
    float* sm = (float*)s_raw;
    float* A = sm;
    float* wt = sm + 4096;
    float* sout = sm + 13312;
    uint32_t wt_addr = smem_u32(wt);
    const int r0 = blockIdx.x * 8, nt = blockIdx.y;
    for (int idx = threadIdx.x; idx < 8 * 128; idx += 256) {
        int m = idx >> 7, q = idx & 127;
        *(float4*)&A[m * 512 + q * 4] =
            *(const float4*)&g_f1[(size_t)(r0 + m) * 512 + q * 4];
    }
    layer_tile8<true>(A, Wb, 512, nt, bb, sout, wt, wt_addr);
    __syncthreads();
    for (int idx = threadIdx.x; idx < 8 * 128; idx += 256) {
        int m = idx >> 7, c = idx & 127;
        g_f2[(size_t)(r0 + m) * 512 + nt * 128 + c] =
            fmaxf(sout[m * 128 + c], 0.0f);
    }
}

__global__ void __launch_bounds__(256, 1)
s1_uv_kernel(const float* __restrict__ Wca) {
    float* sm = (float*)s_raw;
    float* A = sm;
    float* wt = sm + 4096;
    float* sout = sm + 13312;
    uint32_t wt_addr = smem_u32(wt);
    const int r0 = blockIdx.x * 8;
    const int half = blockIdx.y >> 2, nt = blockIdx.y & 3;
    for (int idx = threadIdx.x; idx < 8 * 128; idx += 256) {
        int m = idx >> 7, q = idx & 127;
        *(float4*)&A[m * 512 + q * 4] =
            *(const float4*)&g_f2[(size_t)(r0 + m) * 512 + q * 4];
    }
    layer_tile8<false>(A, Wca + half * 512, 1024, nt, nullptr, sout, wt, wt_addr);
    __syncthreads();
    float* dst = half ? g_v : g_u;
    for (int idx = threadIdx.x; idx < 8 * 128; idx += 256) {
        int m = idx >> 7, c = idx & 127;
        dst[(size_t)(r0 + m) * 512 + nt * 128 + c] = sout[m * 128 + c];
    }
}

// ---------------- prep: fp16-convert + permute weights ---------------------
// piece p = nc*8 + kq (16KB): rows r=0..127 (n = nc*128+r), k = kq*64..+64.
__global__ void prep_kernel(const float* __restrict__ Wcb,
                            const float* __restrict__ Wcc) {
    int gid = blockIdx.x * 256 + threadIdx.x;   // 65536 threads
    for (int e = gid; e < 262144; e += 65536) {
        int n = e >> 9, k = e & 511;
        int nc = n >> 7, r = n & 127, kq = k >> 6, kk = k & 63;
        int c = kk >> 3, w = kk & 7;
        uint32_t dst = (uint32_t)((nc * 8 + kq) * 16384 + r * 128 +
                                  ((c ^ (r & 7)) << 4) + w * 2);
        *(__half*)(g_wcb_h + dst) = __float2half_rn(Wcb[e]);
        *(__half*)(g_wcc_h + dst) = __float2half_rn(Wcc[e]);
    }
}

// ---------------- layer kernels (mma.sync, fp16 single-term, M=64) ---------
// layer1 smem: A 0..64K, Wbuf[2] 64..96K, stage 96..112K      (114688 B)
// layer2 smem: A 0..64K, Wbuf[2] 64..96K, Wout 96..100K, red  (104448 B)
#define SM_A     0
#define SM_WB(b) (65536 + (b) * 16384)
#define SM_STG   98304
#define SM_WOUT  98304
#define SM_RED   102400
#define SMEM1_BYTES 114688
#define SMEM2_BYTES 104448

template <int LAYER>
__global__ void __launch_bounds__(256, 2)
layer_kernel(const float* __restrict__ bca, const float* __restrict__ bias,
             const float* __restrict__ Wout, const float* __restrict__ bout,
             float* __restrict__ out) {
    char* sm = s_raw;
    const uint32_t smem = smem_u32(sm);
    const int tid = threadIdx.x, wid = tid >> 5, lane = tid & 31;
    const int tile = blockIdx.x;
    const int wm = wid & 1;          // M half (32 rows)
    const int wn = wid >> 1;         // N quarter (32 cols of 128-chunk)

    const char* wsrc = (LAYER == 1) ? g_wcb_h : g_wcc_h;

    // -- prologue: W piece 0 (16KB) async; layer2 also A tile (64KB) --
    {
#pragma unroll
        for (int s = 0; s < 4; ++s) {
            int g2 = tid + s * 256;          // 1024 granules
            cp16(smem + SM_WB(0) + g2 * 16, wsrc + g2 * 16);
        }
        if (LAYER == 2) {
            const char* srch = g_e1_h + (size_t)tile * 65536;
#pragma unroll
            for (int s = 0; s < 16; ++s) {
                int o = (tid + s * 256) * 16;
                cp16(smem + SM_A + o, srch + o);
            }
            for (int q = tid; q < 256; q += 256)
                *(float4*)(sm + SM_WOUT + q * 16) = *(const float4*)&Wout[q * 4];
        }
        cp_commit();
    }
    if (LAYER == 1) {
        // build e0 tile (fp16): row r = tid>>2, chunks (tid&3)*16 + s
        const int p0 = tile * TILE_M;
        const int b = p0 / 36864;
        const int rem = p0 - b * 36864;
        const int i = rem / 192, j0 = rem - i * 192;
        const int r = tid >> 2;
        const float* up = g_u + (size_t)(b * 192 + j0 + r) * HD;
        const float* vp = g_v + (size_t)(b * 192 + i) * HD;
        const int cb = (tid & 3) * 16;
#pragma unroll
        for (int s = 0; s < 16; ++s) {
            int chunk = cb + s, k0 = chunk * 8;
            float4 u0 = *(const float4*)(up + k0);
            float4 u1 = *(const float4*)(up + k0 + 4);
            float4 v0 = *(const float4*)(vp + k0);
            float4 v1 = *(const float4*)(vp + k0 + 4);
            float4 c0 = *(const float4*)(bca + k0);
            float4 c1 = *(const float4*)(bca + k0 + 4);
            float x[8] = {u0.x + v0.x + c0.x, u0.y + v0.y + c0.y,
                          u0.z + v0.z + c0.z, u0.w + v0.w + c0.w,
                          u1.x + v1.x + c1.x, u1.y + v1.y + c1.y,
                          u1.z + v1.z + c1.z, u1.w + v1.w + c1.w};
            uint32_t hi4[4];
#pragma unroll
            for (int t = 0; t < 4; ++t) {
                float a0 = fmaxf(x[2 * t], 0.0f);
                float a1 = fmaxf(x[2 * t + 1], 0.0f);
                hi4[t] = pkh(__float2half_rn(a0), __float2half_rn(a1));
            }
            uint32_t off = prow(r, chunk);
            *(uint4*)(sm + SM_A + off) = make_uint4(hi4[0], hi4[1], hi4[2], hi4[3]);
        }
    }

    // lane constants for ldmatrix addressing
    const int a_row = wm * 32 + (lane & 15);
    const int a_half = lane >> 4;
    const int w_rl = (lane & 7) + ((lane >> 4) << 3);
    const int w_half = (lane >> 3) & 1;

    float head[2][2][2];
#pragma unroll
    for (int a2 = 0; a2 < 2; ++a2)
#pragma unroll
        for (int b2 = 0; b2 < 2; ++b2) { head[a2][b2][0] = 0.f; head[a2][b2][1] = 0.f; }

    float acc[2][4][4];

    for (int q = 0; q < 32; ++q) {          // nc = q>>3, kq = q&7 (64 k each)
        const int nc = q >> 3, kq = q & 7, buf = q & 1;
        if (q + 1 < 32) {
            const char* src = wsrc + (size_t)(q + 1) * 16384;
            uint32_t db = smem + SM_WB(buf ^ 1);
#pragma unroll
            for (int s = 0; s < 4; ++s) {
                int g2 = tid + s * 256;
                cp16(db + g2 * 16, src + g2 * 16);
            }
            cp_commit();
            cp_wait1();
        } else {
            cp_wait0();
        }
        __syncthreads();

        if (kq == 0) {
#pragma unroll
            for (int mt = 0; mt < 2; ++mt)
#pragma unroll
                for (int nt = 0; nt < 4; ++nt)
#pragma unroll
                    for (int e = 0; e < 4; ++e) acc[mt][nt][e] = 0.f;
        }

        const uint32_t wb = smem + SM_WB(buf);
#pragma unroll
        for (int k16 = 0; k16 < 4; ++k16) {
            uint32_t ah[2][4], wh[2][4];
            const int achunk = kq * 8 + k16 * 2 + a_half;
#pragma unroll
            for (int mt = 0; mt < 2; ++mt) {
                int row = a_row + mt * 16;
                ldsm_x4(ah[mt], smem + SM_A + prow(row, achunk));
            }
#pragma unroll
            for (int nt = 0; nt < 2; ++nt) {
                int rl = wn * 32 + nt * 16 + w_rl;
                int cc = k16 * 2 + w_half;
                ldsm_x4(wh[nt], wb + prow128(rl, cc));
            }
#pragma unroll
            for (int mt = 0; mt < 2; ++mt)
#pragma unroll
                for (int n8 = 0; n8 < 4; ++n8) {
                    const uint32_t* b2 = &wh[n8 >> 1][(n8 & 1) * 2];
                    mma16816(acc[mt][n8], ah[mt], b2);
                }
        }

        if (kq == 7) {
            // epilogue for this nc
#pragma unroll
            for (int mt = 0; mt < 2; ++mt)
#pragma unroll
                for (int n8 = 0; n8 < 4; ++n8)
#pragma unroll
                    for (int rh = 0; rh < 2; ++rh) {
                        int row = wm * 32 + mt * 16 + (lane >> 2) + rh * 8;
                        int lcol = wn * 32 + n8 * 8 + (lane & 3) * 2;
                        int col = nc * 128 + lcol;
                        float v0 = acc[mt][n8][rh * 2 + 0] + bias[col];
                        float v1 = acc[mt][n8][rh * 2 + 1] + bias[col + 1];
                        v0 = fmaxf(v0, 0.0f);
                        v1 = fmaxf(v1, 0.0f);
                        if (LAYER == 1) {
                            uint32_t off = prow256(row, lcol >> 3) +
                                           (uint32_t)((lcol & 7) * 2);
                            *(uint32_t*)(sm + SM_STG + off) =
                                pkh(__float2half_rn(v0), __float2half_rn(v1));
                        } else {
                            const float* wo = (const float*)(sm + SM_WOUT);
                            head[mt][rh][0] = fmaf(v0, wo[col], head[mt][rh][0]);
                            head[mt][rh][0] = fmaf(v1, wo[col + 1], head[mt][rh][0]);
                            head[mt][rh][1] = fmaf(v0, wo[512 + col], head[mt][rh][1]);
                            head[mt][rh][1] = fmaf(v1, wo[512 + col + 1], head[mt][rh][1]);
                        }
                    }
            if (LAYER == 1) {
                // coalesced copy: stage (64 rows x 256B) -> global blob
                __syncthreads();
                for (int idx = tid; idx < 1024; idx += 256) {
                    int row = idx >> 4, qq = idx & 15;
                    uint4 vh = *(uint4*)(sm + SM_STG + row * 256 + qq * 16);
                    size_t dst = (size_t)tile * 65536 + (size_t)row * 1024 +
                                 (size_t)nc * 256 + qq * 16;
                    *(uint4*)(g_e1_h + dst) = vh;
                }
            }
        }
        __syncthreads();
    }

    if (LAYER == 2) {
        float* red = (float*)(sm + SM_RED);
#pragma unroll
        for (int mt = 0; mt < 2; ++mt)
#pragma unroll
            for (int rh = 0; rh < 2; ++rh)
#pragma unroll
                for (int o = 0; o < 2; ++o) {
                    float s = head[mt][rh][o];
                    s += __shfl_xor_sync(0xffffffffu, s, 1);
                    s += __shfl_xor_sync(0xffffffffu, s, 2);
                    if ((lane & 3) == 0) {
                        int row = wm * 32 + mt * 16 + (lane >> 2) + rh * 8;
                        red[wn * 128 + row * 2 + o] = s;
                    }
                }
        __syncthreads();
        if (tid < 128) {
            int row = tid >> 1, o = tid & 1;
            float s = red[row * 2 + o] + red[128 + row * 2 + o] +
                      red[256 + row * 2 + o] + red[384 + row * 2 + o] + bout[o];
            size_t p = (size_t)tile * TILE_M + row;
            out[p * 2 + o] = s;
        }
    }
}

// ---------------------------------------------------------------------------
extern "C" void kernel_launch(void* const* d_in, const int* in_sizes, int n_in,
                              void* d_out, int out_size) {
    const float* brick = (const float*)d_in[0];
    const float* xy    = (const float*)d_in[1];
    const float* Wxy   = (const float*)d_in[2];
    const float* bxy   = (const float*)d_in[3];
    const float* Wa    = (const float*)d_in[4];
    const float* ba    = (const float*)d_in[5];
    const float* Wb    = (const float*)d_in[6];
    const float* bb    = (const float*)d_in[7];
    const float* Wca   = (const float*)d_in[8];
    const float* bca   = (const float*)d_in[9];
    const float* Wcb   = (const float*)d_in[10];
    const float* bcb   = (const float*)d_in[11];
    const float* Wcc   = (const float*)d_in[12];
    const float* bcc   = (const float*)d_in[13];
    const float* Wout  = (const float*)d_in[14];
    const float* bout  = (const float*)d_in[15];
    float* out = (float*)d_out;

    cudaFuncSetAttribute(s1_f1_kernel,
                         cudaFuncAttributeMaxDynamicSharedMemorySize, S1_SMEM);
    cudaFuncSetAttribute(s1_f2_kernel,
                         cudaFuncAttributeMaxDynamicSharedMemorySize, S1_SMEM);
    cudaFuncSetAttribute(s1_uv_kernel,
                         cudaFuncAttributeMaxDynamicSharedMemorySize, S1_SMEM);
    cudaFuncSetAttribute(layer_kernel<1>,
                         cudaFuncAttributeMaxDynamicSharedMemorySize, SMEM1_BYTES);
    cudaFuncSetAttribute(layer_kernel<2>,
                         cudaFuncAttributeMaxDynamicSharedMemorySize, SMEM2_BYTES);

    prep_kernel<<<256, 256>>>(Wcb, Wcc);
    s1_f1_kernel<<<dim3(96, 4), 256, S1_SMEM>>>(brick, xy, Wxy, bxy, Wa, ba);
    s1_f2_kernel<<<dim3(96, 4), 256, S1_SMEM>>>(Wb, bb);
    s1_uv_kernel<<<dim3(96, 8), 256, S1_SMEM>>>(Wca);
    layer_kernel<1><<<N_TILES2, 256, SMEM1_BYTES>>>(bca, bcb, nullptr, nullptr, nullptr);
    layer_kernel<2><<<N_TILES2, 256, SMEM2_BYTES>>>(bca, bcc, Wout, bout, out);
}